// round 1
// baseline (speedup 1.0000x reference)
#include <cuda_runtime.h>
#include <math.h>

#define HDIM 1024
#define IC   4096
#define PH   4096
#define TH   2048
#define NTILES 30
#define MAXM 14592

// Scratch (allocation-free per harness rules)
__device__ int   g_meta[NTILES * 4];                 // h, w, in_off, out_off per tile
__device__ float g_X[(size_t)MAXM * IC];             // post-LN activations
__device__ float g_H[(size_t)MAXM * PH];             // post-GELU hidden

// ---------------------------------------------------------------------------
// Tile metadata: prefix sums over the 30 ragged tiles.
// Auto-detect int32 vs int64 spatial_shapes: first shape is (16,16); if the
// buffer is int64 little-endian, word[1] is the high word == 0.
// ---------------------------------------------------------------------------
__global__ void meta_kernel(const int* __restrict__ ss) {
    if (threadIdx.x == 0 && blockIdx.x == 0) {
        int is64 = (ss[1] == 0) ? 1 : 0;
        int in_off = 0, out_off = 0;
        for (int t = 0; t < NTILES; t++) {
            int h, w;
            if (is64) { h = ss[4 * t]; w = ss[4 * t + 2]; }
            else      { h = ss[2 * t]; w = ss[2 * t + 1]; }
            g_meta[4 * t + 0] = h;
            g_meta[4 * t + 1] = w;
            g_meta[4 * t + 2] = in_off;
            g_meta[4 * t + 3] = out_off;
            in_off  += h * w;
            out_off += (h >> 1) * (w >> 1);
        }
    }
}

// ---------------------------------------------------------------------------
// Fused pixel-unshuffle gather + LayerNorm(4096) -> g_X
// One block per output row; 256 threads, 16 features each, values held in
// registers between the stat pass and the normalize pass.
// ---------------------------------------------------------------------------
__global__ void __launch_bounds__(256) gather_ln_kernel(
    const float* __restrict__ vf,
    const float* __restrict__ gamma,
    const float* __restrict__ beta)
{
    const int r   = blockIdx.x;
    const int tid = threadIdx.x;

    __shared__ int   srows[4];
    __shared__ float sred[2][8];
    __shared__ float sstat[2];

    if (tid == 0) {
        int t = 0;
        #pragma unroll 1
        for (int i = 0; i < NTILES; i++) {
            int h  = g_meta[4 * i + 0];
            int w  = g_meta[4 * i + 1];
            int oo = g_meta[4 * i + 3];
            int cnt = (h >> 1) * (w >> 1);
            if (r >= oo && r < oo + cnt) { t = i; break; }
        }
        int h  = g_meta[4 * t + 0];
        int w  = g_meta[4 * t + 1];
        int io = g_meta[4 * t + 2];
        int oo = g_meta[4 * t + 3];
        int local = r - oo;
        int wb = w >> 1;
        int bh = local / wb;
        int bw = local - bh * wb;
        srows[0] = io + (2 * bh)     * w + 2 * bw;
        srows[1] = io + (2 * bh)     * w + 2 * bw + 1;
        srows[2] = io + (2 * bh + 1) * w + 2 * bw;
        srows[3] = io + (2 * bh + 1) * w + 2 * bw + 1;
    }
    __syncthreads();

    float vals[16];
    float s = 0.f, s2 = 0.f;
    #pragma unroll
    for (int i = 0; i < 16; i++) {
        int f      = tid + i * 256;
        int c      = f >> 10;
        int within = f & 1023;
        float v = vf[(size_t)srows[c] * HDIM + within];
        vals[i] = v;
        s  += v;
        s2 += v * v;
    }

    #pragma unroll
    for (int o = 16; o > 0; o >>= 1) {
        s  += __shfl_down_sync(0xFFFFFFFFu, s, o);
        s2 += __shfl_down_sync(0xFFFFFFFFu, s2, o);
    }
    if ((tid & 31) == 0) { sred[0][tid >> 5] = s; sred[1][tid >> 5] = s2; }
    __syncthreads();
    if (tid < 32) {
        float a = (tid < 8) ? sred[0][tid] : 0.f;
        float b = (tid < 8) ? sred[1][tid] : 0.f;
        #pragma unroll
        for (int o = 4; o > 0; o >>= 1) {
            a += __shfl_down_sync(0xFFFFFFFFu, a, o);
            b += __shfl_down_sync(0xFFFFFFFFu, b, o);
        }
        if (tid == 0) {
            float mu  = a * (1.0f / IC);
            float var = b * (1.0f / IC) - mu * mu;
            sstat[0] = mu;
            sstat[1] = rsqrtf(var + 1e-5f);
        }
    }
    __syncthreads();

    float mu   = sstat[0];
    float rstd = sstat[1];
    float* xo = g_X + (size_t)r * IC;
    #pragma unroll
    for (int i = 0; i < 16; i++) {
        int f = tid + i * 256;
        xo[f] = (vals[i] - mu) * rstd * gamma[f] + beta[f];
    }
}

// ---------------------------------------------------------------------------
// fp32 SGEMM: C = epi(A @ B + bias)
// A: M x K row-major, B: K x N row-major.
// 128x128 block tile, BK=8, 256 threads, 8x8 per thread (split 4+4 quadrants
// for conflict-free float4 fragment reads).
// ---------------------------------------------------------------------------
__device__ __forceinline__ float gelu_exact(float x) {
    return 0.5f * x * (1.0f + erff(x * 0.70710678118654752440f));
}

__global__ void __launch_bounds__(256) sgemm_kernel(
    const float* __restrict__ A,
    const float* __restrict__ B,
    const float* __restrict__ bias,
    float* __restrict__ C,
    int M, int N, int K, int dogelu)
{
    __shared__ float As[8][128];
    __shared__ float Bs[8][128];

    const int tid = threadIdx.x;
    const int tx  = tid & 15;
    const int ty  = tid >> 4;
    const int bn  = blockIdx.x * 128;
    const int bm  = blockIdx.y * 128;

    // A tile load mapping: 128 rows x 8 cols, one float4 per thread
    const int arow = tid >> 1;
    const int acol = (tid & 1) * 4;
    // B tile load mapping: 8 rows x 128 cols, one float4 per thread
    const int brow = tid >> 5;
    const int bcol = (tid & 31) * 4;

    int aRowG = bm + arow;
    if (aRowG >= M) aRowG = M - 1;   // clamp (valid memory; results masked at store)
    const float* Aptr = A + (size_t)aRowG * K + acol;
    const float* Bptr = B + (size_t)brow * N + bn + bcol;

    float acc[8][8];
    #pragma unroll
    for (int i = 0; i < 8; i++)
        #pragma unroll
        for (int j = 0; j < 8; j++) acc[i][j] = 0.f;

    for (int k0 = 0; k0 < K; k0 += 8) {
        float4 av = *(const float4*)(Aptr + k0);
        float4 bv = *(const float4*)(Bptr + (size_t)k0 * N);
        As[acol + 0][arow] = av.x;
        As[acol + 1][arow] = av.y;
        As[acol + 2][arow] = av.z;
        As[acol + 3][arow] = av.w;
        *(float4*)&Bs[brow][bcol] = bv;
        __syncthreads();

        #pragma unroll
        for (int kk = 0; kk < 8; kk++) {
            float a[8], b[8];
            *(float4*)&a[0] = *(const float4*)&As[kk][ty * 4];
            *(float4*)&a[4] = *(const float4*)&As[kk][64 + ty * 4];
            *(float4*)&b[0] = *(const float4*)&Bs[kk][tx * 4];
            *(float4*)&b[4] = *(const float4*)&Bs[kk][64 + tx * 4];
            #pragma unroll
            for (int i = 0; i < 8; i++)
                #pragma unroll
                for (int j = 0; j < 8; j++)
                    acc[i][j] += a[i] * b[j];
        }
        __syncthreads();
    }

    #pragma unroll
    for (int i = 0; i < 8; i++) {
        int row = bm + ((i < 4) ? (ty * 4 + i) : (64 + ty * 4 + i - 4));
        if (row >= M) continue;
        #pragma unroll
        for (int jq = 0; jq < 2; jq++) {
            int col = bn + (jq ? (64 + tx * 4) : (tx * 4));
            float4 v;
            v.x = acc[i][jq * 4 + 0] + bias[col + 0];
            v.y = acc[i][jq * 4 + 1] + bias[col + 1];
            v.z = acc[i][jq * 4 + 2] + bias[col + 2];
            v.w = acc[i][jq * 4 + 3] + bias[col + 3];
            if (dogelu) {
                v.x = gelu_exact(v.x);
                v.y = gelu_exact(v.y);
                v.z = gelu_exact(v.z);
                v.w = gelu_exact(v.w);
            }
            *(float4*)(C + (size_t)row * N + col) = v;
        }
    }
}

// ---------------------------------------------------------------------------
// Launch
// ---------------------------------------------------------------------------
extern "C" void kernel_launch(void* const* d_in, const int* in_sizes, int n_in,
                              void* d_out, int out_size)
{
    const float* vf    = (const float*)d_in[0];
    const int*   ss    = (const int*)  d_in[1];
    const float* gamma = (const float*)d_in[2];
    const float* beta  = (const float*)d_in[3];
    const float* w1    = (const float*)d_in[4];
    const float* b1    = (const float*)d_in[5];
    const float* w2    = (const float*)d_in[6];
    const float* b2    = (const float*)d_in[7];
    float* out = (float*)d_out;

    int total_tokens = in_sizes[0] / HDIM;
    int M = total_tokens / 4;
    if (M > MAXM) M = MAXM;

    float *dX = nullptr, *dH = nullptr;
    cudaGetSymbolAddress((void**)&dX, g_X);
    cudaGetSymbolAddress((void**)&dH, g_H);

    meta_kernel<<<1, 32>>>(ss);
    gather_ln_kernel<<<M, 256>>>(vf, gamma, beta);

    dim3 g1(PH / 128, (M + 127) / 128);
    sgemm_kernel<<<g1, 256>>>(dX, w1, b1, dH, M, PH, IC, 1);

    dim3 g2(TH / 128, (M + 127) / 128);
    sgemm_kernel<<<g2, 256>>>(dH, w2, b2, out, M, TH, PH, 0);
}

// round 7
// speedup vs baseline: 3.2242x; 3.2242x over previous
#include <cuda_runtime.h>
#include <math.h>
#include <stdint.h>

#define HDIM 1024
#define IC   4096
#define PH   4096
#define TH   2048
#define NTILES 30
#define MAXM 14592

// ------------------------- device scratch (no allocs) -----------------------
__device__ int   g_meta[NTILES * 4];
__device__ float g_X [(size_t)MAXM * IC];   // post-LN, tf32-rounded fp32
__device__ float g_H [(size_t)MAXM * PH];   // post-GELU, tf32-rounded fp32
__device__ float g_W1[(size_t)IC * PH];     // tf32-rounded W1 [K,N]
__device__ float g_W2[(size_t)PH * TH];     // tf32-rounded W2 [K,N]

// ------------------------------ helpers ------------------------------------
__device__ __forceinline__ float gelu_exact(float x) {
    return 0.5f * x * (1.0f + erff(x * 0.70710678118654752440f));
}

__device__ __forceinline__ float tf32_round(float x) {
    uint32_t r;
    asm("cvt.rna.tf32.f32 %0, %1;" : "=r"(r) : "f"(x));
    return __uint_as_float(r);
}

__device__ __forceinline__ void cp16(void* smem_dst, const void* gmem_src) {
    uint32_t d = (uint32_t)__cvta_generic_to_shared(smem_dst);
    asm volatile("cp.async.cg.shared.global [%0], [%1], 16;" :: "r"(d), "l"(gmem_src) : "memory");
}
__device__ __forceinline__ void cp_commit() {
    asm volatile("cp.async.commit_group;" ::: "memory");
}
template <int N>
__device__ __forceinline__ void cp_wait() {
    asm volatile("cp.async.wait_group %0;" :: "n"(N) : "memory");
}

__device__ __forceinline__ void mma_tf32(float* c, const uint32_t* a, const uint32_t* b) {
    asm volatile(
        "mma.sync.aligned.m16n8k8.row.col.f32.tf32.tf32.f32 "
        "{%0,%1,%2,%3}, {%4,%5,%6,%7}, {%8,%9}, {%0,%1,%2,%3};"
        : "+f"(c[0]), "+f"(c[1]), "+f"(c[2]), "+f"(c[3])
        : "r"(a[0]), "r"(a[1]), "r"(a[2]), "r"(a[3]), "r"(b[0]), "r"(b[1]));
}

// ----------------------------------------------------------------------------
// meta kernel (prefix sums over ragged tiles; int32/int64 auto-detect)
// ----------------------------------------------------------------------------
__global__ void meta_kernel(const int* __restrict__ ss) {
    if (threadIdx.x == 0 && blockIdx.x == 0) {
        int is64 = (ss[1] == 0) ? 1 : 0;
        int in_off = 0, out_off = 0;
        for (int t = 0; t < NTILES; t++) {
            int h, w;
            if (is64) { h = ss[4 * t]; w = ss[4 * t + 2]; }
            else      { h = ss[2 * t]; w = ss[2 * t + 1]; }
            g_meta[4 * t + 0] = h;
            g_meta[4 * t + 1] = w;
            g_meta[4 * t + 2] = in_off;
            g_meta[4 * t + 3] = out_off;
            in_off  += h * w;
            out_off += (h >> 1) * (w >> 1);
        }
    }
}

// ----------------------------------------------------------------------------
// gather + LayerNorm -> tf32-rounded fp32 activations
// ----------------------------------------------------------------------------
__global__ void __launch_bounds__(256) gather_ln_kernel(
    const float* __restrict__ vf,
    const float* __restrict__ gamma,
    const float* __restrict__ beta)
{
    const int r   = blockIdx.x;
    const int tid = threadIdx.x;

    __shared__ int   srows[4];
    __shared__ float sred[2][8];
    __shared__ float sstat[2];

    if (tid == 0) {
        int t = 0;
        #pragma unroll 1
        for (int i = 0; i < NTILES; i++) {
            int h  = g_meta[4 * i + 0];
            int w  = g_meta[4 * i + 1];
            int oo = g_meta[4 * i + 3];
            int cnt = (h >> 1) * (w >> 1);
            if (r >= oo && r < oo + cnt) { t = i; break; }
        }
        int w  = g_meta[4 * t + 1];
        int io = g_meta[4 * t + 2];
        int oo = g_meta[4 * t + 3];
        int local = r - oo;
        int wb = w >> 1;
        int bh = local / wb;
        int bw = local - bh * wb;
        srows[0] = io + (2 * bh)     * w + 2 * bw;
        srows[1] = io + (2 * bh)     * w + 2 * bw + 1;
        srows[2] = io + (2 * bh + 1) * w + 2 * bw;
        srows[3] = io + (2 * bh + 1) * w + 2 * bw + 1;
    }
    __syncthreads();

    float vals[16];
    float s = 0.f, s2 = 0.f;
    #pragma unroll
    for (int i = 0; i < 16; i++) {
        int f      = tid + i * 256;
        int c      = f >> 10;
        int within = f & 1023;
        float v = vf[(size_t)srows[c] * HDIM + within];
        vals[i] = v;
        s  += v;
        s2 += v * v;
    }

    #pragma unroll
    for (int o = 16; o > 0; o >>= 1) {
        s  += __shfl_down_sync(0xFFFFFFFFu, s, o);
        s2 += __shfl_down_sync(0xFFFFFFFFu, s2, o);
    }
    if ((tid & 31) == 0) { sred[0][tid >> 5] = s; sred[1][tid >> 5] = s2; }
    __syncthreads();
    if (tid < 32) {
        float a = (tid < 8) ? sred[0][tid] : 0.f;
        float b = (tid < 8) ? sred[1][tid] : 0.f;
        #pragma unroll
        for (int o = 4; o > 0; o >>= 1) {
            a += __shfl_down_sync(0xFFFFFFFFu, a, o);
            b += __shfl_down_sync(0xFFFFFFFFu, b, o);
        }
        if (tid == 0) {
            float mu  = a * (1.0f / IC);
            float var = b * (1.0f / IC) - mu * mu;
            sstat[0] = mu;
            sstat[1] = rsqrtf(var + 1e-5f);
        }
    }
    __syncthreads();

    float mu   = sstat[0];
    float rstd = sstat[1];
    float* xo = g_X + (size_t)r * IC;
    #pragma unroll
    for (int i = 0; i < 16; i++) {
        int f = tid + i * 256;
        float y = (vals[i] - mu) * rstd * gamma[f] + beta[f];
        xo[f] = tf32_round(y);
    }
}

// ----------------------------------------------------------------------------
// elementwise tf32 rounding of weights (keeps [K,N] layout)
// ----------------------------------------------------------------------------
__global__ void __launch_bounds__(256) wround_kernel(
    const float* __restrict__ W, float* __restrict__ Wt, int n)
{
    int i = blockIdx.x * 1024 + threadIdx.x * 4;
    if (i + 3 < n) {
        float4 v = *(const float4*)(W + i);
        v.x = tf32_round(v.x);
        v.y = tf32_round(v.y);
        v.z = tf32_round(v.z);
        v.w = tf32_round(v.w);
        *(float4*)(Wt + i) = v;
    }
}

// ----------------------------------------------------------------------------
// tf32 mma.sync GEMM:  C[M,N] = epi( A[M,K] @ B[K,N] + bias )
//   CTA tile 128x128, BK=16, 2-stage cp.async, 8 warps (4M x 2N), warp 32x64.
//   mode 1: +bias, exact GELU, tf32-round -> out.   mode 0: +bias -> out.
// ----------------------------------------------------------------------------
#define BK 16

__global__ void __launch_bounds__(256, 2) gemm_kernel(
    const float* __restrict__ A,
    const float* __restrict__ B,
    const float* __restrict__ bias,
    float* __restrict__ out,
    int M, int K, int Nfull, int mode)
{
    __shared__ float As[2][128][20];    // [m][k], pad 20 (16B-aligned rows)
    __shared__ float Bs[2][BK][136];    // [k][n], pad 136 (16B-aligned rows)

    const int tid  = threadIdx.x;
    const int wid  = tid >> 5;
    const int lane = tid & 31;
    const int g    = lane >> 2;          // group 0..7
    const int t    = lane & 3;           // 0..3
    const int wm   = wid & 3;            // 4 warps along M
    const int wn   = wid >> 2;           // 2 warps along N
    const int bm   = blockIdx.y * 128;
    const int bn   = blockIdx.x * 128;
    const int nk   = K / BK;

    float c[2][8][4];
    #pragma unroll
    for (int i = 0; i < 2; i++)
        #pragma unroll
        for (int j = 0; j < 8; j++)
            #pragma unroll
            for (int q = 0; q < 4; q++) c[i][j][q] = 0.f;

    // ---- stage loader: A 128x16 (512 f4), B 16x128 (512 f4); 2 f4 each/thr
    auto load_stage = [&](int kt, int st) {
        int k0 = kt * BK;
        #pragma unroll
        for (int i = 0; i < 2; i++) {
            int idx = tid + 256 * i;
            int m  = idx >> 2, kq = idx & 3;
            cp16(&As[st][m][kq * 4], A + (size_t)(bm + m) * K + k0 + kq * 4);
            int kk = idx >> 5, nq = idx & 31;
            cp16(&Bs[st][kk][nq * 4], B + (size_t)(k0 + kk) * Nfull + bn + nq * 4);
        }
        cp_commit();
    };

    load_stage(0, 0);

    for (int kt = 0; kt < nk; ++kt) {
        int st = kt & 1;
        if (kt + 1 < nk) {
            load_stage(kt + 1, (kt + 1) & 1);
            cp_wait<1>();
        } else {
            cp_wait<0>();
        }
        __syncthreads();

        #pragma unroll
        for (int ks = 0; ks < 2; ++ks) {
            const int kb = ks * 8;
            uint32_t a[2][4], b[8][2];
            #pragma unroll
            for (int mt = 0; mt < 2; ++mt) {
                int m0 = wm * 32 + mt * 16;
                a[mt][0] = __float_as_uint(As[st][m0 + g    ][kb + t    ]);
                a[mt][1] = __float_as_uint(As[st][m0 + g + 8][kb + t    ]);
                a[mt][2] = __float_as_uint(As[st][m0 + g    ][kb + t + 4]);
                a[mt][3] = __float_as_uint(As[st][m0 + g + 8][kb + t + 4]);
            }
            #pragma unroll
            for (int nt = 0; nt < 8; ++nt) {
                int n0 = wn * 64 + nt * 8 + g;
                b[nt][0] = __float_as_uint(Bs[st][kb + t    ][n0]);
                b[nt][1] = __float_as_uint(Bs[st][kb + t + 4][n0]);
            }
            #pragma unroll
            for (int mt = 0; mt < 2; ++mt)
                #pragma unroll
                for (int nt = 0; nt < 8; ++nt)
                    mma_tf32(c[mt][nt], a[mt], b[nt]);
        }
        __syncthreads();
    }

    // ---------------------- epilogue ----------------------
    #pragma unroll
    for (int mt = 0; mt < 2; ++mt) {
        int r0 = bm + wm * 32 + mt * 16 + g;
        #pragma unroll
        for (int nt = 0; nt < 8; ++nt) {
            int n0 = bn + wn * 64 + nt * 8 + t * 2;
            float b0 = bias[n0], b1 = bias[n0 + 1];
            float v00 = c[mt][nt][0] + b0, v01 = c[mt][nt][1] + b1;
            float v10 = c[mt][nt][2] + b0, v11 = c[mt][nt][3] + b1;
            if (mode) {
                v00 = tf32_round(gelu_exact(v00));
                v01 = tf32_round(gelu_exact(v01));
                v10 = tf32_round(gelu_exact(v10));
                v11 = tf32_round(gelu_exact(v11));
            }
            *(float2*)(out + (size_t)r0 * Nfull + n0)       = make_float2(v00, v01);
            *(float2*)(out + (size_t)(r0 + 8) * Nfull + n0) = make_float2(v10, v11);
        }
    }
}

// ----------------------------------------------------------------------------
// launch
// ----------------------------------------------------------------------------
extern "C" void kernel_launch(void* const* d_in, const int* in_sizes, int n_in,
                              void* d_out, int out_size)
{
    const float* vf    = (const float*)d_in[0];
    const int*   ss    = (const int*)  d_in[1];
    const float* gamma = (const float*)d_in[2];
    const float* beta  = (const float*)d_in[3];
    const float* w1    = (const float*)d_in[4];
    const float* b1    = (const float*)d_in[5];
    const float* w2    = (const float*)d_in[6];
    const float* b2    = (const float*)d_in[7];
    float* out = (float*)d_out;

    int total_tokens = in_sizes[0] / HDIM;
    int M = total_tokens / 4;
    if (M > MAXM) M = MAXM;

    float *dX, *dH, *dW1, *dW2;
    cudaGetSymbolAddress((void**)&dX,  g_X);
    cudaGetSymbolAddress((void**)&dH,  g_H);
    cudaGetSymbolAddress((void**)&dW1, g_W1);
    cudaGetSymbolAddress((void**)&dW2, g_W2);

    meta_kernel<<<1, 32>>>(ss);
    gather_ln_kernel<<<M, 256>>>(vf, gamma, beta);

    wround_kernel<<<(IC * PH + 1023) / 1024, 256>>>(w1, dW1, IC * PH);
    wround_kernel<<<(PH * TH + 1023) / 1024, 256>>>(w2, dW2, PH * TH);

    dim3 g1(PH / 128, M / 128);
    gemm_kernel<<<g1, 256>>>(dX, dW1, b1, dH, M, IC, PH, 1);

    dim3 g2(TH / 128, M / 128);
    gemm_kernel<<<g2, 256>>>(dH, dW2, b2, out, M, PH, TH, 0);
}

// round 9
// speedup vs baseline: 3.2395x; 1.0047x over previous
#include <cuda_runtime.h>
#include <math.h>
#include <stdint.h>

#define HDIM 1024
#define IC   4096
#define PH   4096
#define TH   2048
#define NTILES 30
#define MAXM 14592

// ------------------------- device scratch (no allocs) -----------------------
__device__ int   g_meta[NTILES * 4];
__device__ float g_X [(size_t)MAXM * IC];   // post-LN, tf32-rounded fp32
__device__ float g_H [(size_t)MAXM * PH];   // post-GELU, tf32-rounded fp32
__device__ float g_W1[(size_t)IC * PH];     // tf32-rounded W1 [K,N]
__device__ float g_W2[(size_t)PH * TH];     // tf32-rounded W2 [K,N]

// ------------------------------ helpers ------------------------------------
__device__ __forceinline__ float gelu_exact(float x) {
    return 0.5f * x * (1.0f + erff(x * 0.70710678118654752440f));
}

__device__ __forceinline__ float tf32_round(float x) {
    uint32_t r;
    asm("cvt.rna.tf32.f32 %0, %1;" : "=r"(r) : "f"(x));
    return __uint_as_float(r);
}

__device__ __forceinline__ void cp16(void* smem_dst, const void* gmem_src) {
    uint32_t d = (uint32_t)__cvta_generic_to_shared(smem_dst);
    asm volatile("cp.async.cg.shared.global [%0], [%1], 16;" :: "r"(d), "l"(gmem_src) : "memory");
}
__device__ __forceinline__ void cp_commit() {
    asm volatile("cp.async.commit_group;" ::: "memory");
}
template <int N>
__device__ __forceinline__ void cp_wait() {
    asm volatile("cp.async.wait_group %0;" :: "n"(N) : "memory");
}

__device__ __forceinline__ void mma_tf32(float* c, const uint32_t* a, const uint32_t* b) {
    asm volatile(
        "mma.sync.aligned.m16n8k8.row.col.f32.tf32.tf32.f32 "
        "{%0,%1,%2,%3}, {%4,%5,%6,%7}, {%8,%9}, {%0,%1,%2,%3};"
        : "+f"(c[0]), "+f"(c[1]), "+f"(c[2]), "+f"(c[3])
        : "r"(a[0]), "r"(a[1]), "r"(a[2]), "r"(a[3]), "r"(b[0]), "r"(b[1]));
}

// ----------------------------------------------------------------------------
// meta kernel (prefix sums over ragged tiles; int32/int64 auto-detect)
// ----------------------------------------------------------------------------
__global__ void meta_kernel(const int* __restrict__ ss) {
    if (threadIdx.x == 0 && blockIdx.x == 0) {
        int is64 = (ss[1] == 0) ? 1 : 0;
        int in_off = 0, out_off = 0;
        for (int t = 0; t < NTILES; t++) {
            int h, w;
            if (is64) { h = ss[4 * t]; w = ss[4 * t + 2]; }
            else      { h = ss[2 * t]; w = ss[2 * t + 1]; }
            g_meta[4 * t + 0] = h;
            g_meta[4 * t + 1] = w;
            g_meta[4 * t + 2] = in_off;
            g_meta[4 * t + 3] = out_off;
            in_off  += h * w;
            out_off += (h >> 1) * (w >> 1);
        }
    }
}

// ----------------------------------------------------------------------------
// gather + LayerNorm -> tf32-rounded fp32 activations
// ----------------------------------------------------------------------------
__global__ void __launch_bounds__(256) gather_ln_kernel(
    const float* __restrict__ vf,
    const float* __restrict__ gamma,
    const float* __restrict__ beta)
{
    const int r   = blockIdx.x;
    const int tid = threadIdx.x;

    __shared__ int   srows[4];
    __shared__ float sred[2][8];
    __shared__ float sstat[2];

    if (tid == 0) {
        int t = 0;
        #pragma unroll 1
        for (int i = 0; i < NTILES; i++) {
            int h  = g_meta[4 * i + 0];
            int w  = g_meta[4 * i + 1];
            int oo = g_meta[4 * i + 3];
            int cnt = (h >> 1) * (w >> 1);
            if (r >= oo && r < oo + cnt) { t = i; break; }
        }
        int w  = g_meta[4 * t + 1];
        int io = g_meta[4 * t + 2];
        int oo = g_meta[4 * t + 3];
        int local = r - oo;
        int wb = w >> 1;
        int bh = local / wb;
        int bw = local - bh * wb;
        srows[0] = io + (2 * bh)     * w + 2 * bw;
        srows[1] = io + (2 * bh)     * w + 2 * bw + 1;
        srows[2] = io + (2 * bh + 1) * w + 2 * bw;
        srows[3] = io + (2 * bh + 1) * w + 2 * bw + 1;
    }
    __syncthreads();

    float vals[16];
    float s = 0.f, s2 = 0.f;
    #pragma unroll
    for (int i = 0; i < 16; i++) {
        int f      = tid + i * 256;
        int c      = f >> 10;
        int within = f & 1023;
        float v = vf[(size_t)srows[c] * HDIM + within];
        vals[i] = v;
        s  += v;
        s2 += v * v;
    }

    #pragma unroll
    for (int o = 16; o > 0; o >>= 1) {
        s  += __shfl_down_sync(0xFFFFFFFFu, s, o);
        s2 += __shfl_down_sync(0xFFFFFFFFu, s2, o);
    }
    if ((tid & 31) == 0) { sred[0][tid >> 5] = s; sred[1][tid >> 5] = s2; }
    __syncthreads();
    if (tid < 32) {
        float a = (tid < 8) ? sred[0][tid] : 0.f;
        float b = (tid < 8) ? sred[1][tid] : 0.f;
        #pragma unroll
        for (int o = 4; o > 0; o >>= 1) {
            a += __shfl_down_sync(0xFFFFFFFFu, a, o);
            b += __shfl_down_sync(0xFFFFFFFFu, b, o);
        }
        if (tid == 0) {
            float mu  = a * (1.0f / IC);
            float var = b * (1.0f / IC) - mu * mu;
            sstat[0] = mu;
            sstat[1] = rsqrtf(var + 1e-5f);
        }
    }
    __syncthreads();

    float mu   = sstat[0];
    float rstd = sstat[1];
    float* xo = g_X + (size_t)r * IC;
    #pragma unroll
    for (int i = 0; i < 16; i++) {
        int f = tid + i * 256;
        float y = (vals[i] - mu) * rstd * gamma[f] + beta[f];
        xo[f] = tf32_round(y);
    }
}

// ----------------------------------------------------------------------------
// elementwise tf32 rounding of weights (keeps [K,N] layout)
// ----------------------------------------------------------------------------
__global__ void __launch_bounds__(256) wround_kernel(
    const float* __restrict__ W, float* __restrict__ Wt, int n)
{
    int i = blockIdx.x * 1024 + threadIdx.x * 4;
    if (i + 3 < n) {
        float4 v = *(const float4*)(W + i);
        v.x = tf32_round(v.x);
        v.y = tf32_round(v.y);
        v.z = tf32_round(v.z);
        v.w = tf32_round(v.w);
        *(float4*)(Wt + i) = v;
    }
}

// ----------------------------------------------------------------------------
// tf32 mma.sync GEMM:  C[M,N] = epi( A[M,K] @ B[K,N] + bias )
//   CTA tile 128x128, BK=16, 4-stage cp.async (3 groups in flight, empty tail
//   commits keep the count invariant), ONE __syncthreads per k-tile.
//   8 warps (4M x 2N), warp tile 32x64.
//   mode 1: +bias, exact GELU, tf32-round -> out.   mode 0: +bias -> out.
// ----------------------------------------------------------------------------
#define BK 16
#define NSTAGE 4
#define AST 2560        // floats per A stage: 128 rows * 20
#define BST 2176        // floats per B stage: 16 rows * 136
#define ABYTES (NSTAGE * AST)            // A region floats
#define DSMEMF (NSTAGE * (AST + BST))    // total floats
#define DSMEMB (DSMEMF * 4)              // 75776 bytes

__global__ void __launch_bounds__(256, 2) gemm_kernel(
    const float* __restrict__ A,
    const float* __restrict__ B,
    const float* __restrict__ bias,
    float* __restrict__ out,
    int M, int K, int Nfull, int mode)
{
    extern __shared__ float dsm[];
    float* Asm = dsm;                 // [NSTAGE][128][20]
    float* Bsm = dsm + ABYTES;        // [NSTAGE][16][136]

    const int tid  = threadIdx.x;
    const int wid  = tid >> 5;
    const int lane = tid & 31;
    const int g    = lane >> 2;          // 0..7
    const int t    = lane & 3;           // 0..3
    const int wm   = wid & 3;            // 4 warps along M
    const int wn   = wid >> 2;           // 2 warps along N
    const int bm   = blockIdx.y * 128;
    const int bn   = blockIdx.x * 128;
    const int nk   = K / BK;

    float c[2][8][4];
    #pragma unroll
    for (int i = 0; i < 2; i++)
        #pragma unroll
        for (int j = 0; j < 8; j++)
            #pragma unroll
            for (int q = 0; q < 4; q++) c[i][j][q] = 0.f;

    // per-thread load coords (2 x float4 for A, 2 x float4 for B)
    auto load_stage = [&](int kt) {
        int st = kt & (NSTAGE - 1);
        int k0 = kt * BK;
        float* As = Asm + st * AST;
        float* Bs = Bsm + st * BST;
        #pragma unroll
        for (int i = 0; i < 2; i++) {
            int idx = tid + 256 * i;
            int m  = idx >> 2, kq = idx & 3;
            cp16(As + m * 20 + kq * 4, A + (size_t)(bm + m) * K + k0 + kq * 4);
            int kk = idx >> 5, nq = idx & 31;
            cp16(Bs + kk * 136 + nq * 4, B + (size_t)(k0 + kk) * Nfull + bn + nq * 4);
        }
        cp_commit();
    };

    // prologue: 3 stages in flight
    load_stage(0);
    load_stage(1);
    load_stage(2);

    for (int kt = 0; kt < nk; ++kt) {
        cp_wait<2>();            // oldest (stage kt) complete; 2 remain
        __syncthreads();         // all warps done with buffer (kt-1)&3 too

        if (kt + 3 < nk) load_stage(kt + 3);   // overlaps with compute below
        else             cp_commit();          // empty group keeps invariant

        const int st = kt & (NSTAGE - 1);
        const float* As = Asm + st * AST;
        const float* Bs = Bsm + st * BST;

        #pragma unroll
        for (int ks = 0; ks < 2; ++ks) {
            const int kb = ks * 8;
            uint32_t a[2][4], b[8][2];
            #pragma unroll
            for (int mt = 0; mt < 2; ++mt) {
                int m0 = wm * 32 + mt * 16;
                a[mt][0] = __float_as_uint(As[(m0 + g    ) * 20 + kb + t    ]);
                a[mt][1] = __float_as_uint(As[(m0 + g + 8) * 20 + kb + t    ]);
                a[mt][2] = __float_as_uint(As[(m0 + g    ) * 20 + kb + t + 4]);
                a[mt][3] = __float_as_uint(As[(m0 + g + 8) * 20 + kb + t + 4]);
            }
            #pragma unroll
            for (int nt = 0; nt < 8; ++nt) {
                int n0 = wn * 64 + nt * 8 + g;
                b[nt][0] = __float_as_uint(Bs[(kb + t    ) * 136 + n0]);
                b[nt][1] = __float_as_uint(Bs[(kb + t + 4) * 136 + n0]);
            }
            #pragma unroll
            for (int mt = 0; mt < 2; ++mt)
                #pragma unroll
                for (int nt = 0; nt < 8; ++nt)
                    mma_tf32(c[mt][nt], a[mt], b[nt]);
        }
    }
    cp_wait<0>();   // drain tail empty groups

    // ---------------------- epilogue ----------------------
    #pragma unroll
    for (int mt = 0; mt < 2; ++mt) {
        int r0 = bm + wm * 32 + mt * 16 + g;
        #pragma unroll
        for (int nt = 0; nt < 8; ++nt) {
            int n0 = bn + wn * 64 + nt * 8 + t * 2;
            float b0 = bias[n0], b1 = bias[n0 + 1];
            float v00 = c[mt][nt][0] + b0, v01 = c[mt][nt][1] + b1;
            float v10 = c[mt][nt][2] + b0, v11 = c[mt][nt][3] + b1;
            if (mode) {
                v00 = tf32_round(gelu_exact(v00));
                v01 = tf32_round(gelu_exact(v01));
                v10 = tf32_round(gelu_exact(v10));
                v11 = tf32_round(gelu_exact(v11));
            }
            *(float2*)(out + (size_t)r0 * Nfull + n0)       = make_float2(v00, v01);
            *(float2*)(out + (size_t)(r0 + 8) * Nfull + n0) = make_float2(v10, v11);
        }
    }
}

// ----------------------------------------------------------------------------
// launch
// ----------------------------------------------------------------------------
extern "C" void kernel_launch(void* const* d_in, const int* in_sizes, int n_in,
                              void* d_out, int out_size)
{
    const float* vf    = (const float*)d_in[0];
    const int*   ss    = (const int*)  d_in[1];
    const float* gamma = (const float*)d_in[2];
    const float* beta  = (const float*)d_in[3];
    const float* w1    = (const float*)d_in[4];
    const float* b1    = (const float*)d_in[5];
    const float* w2    = (const float*)d_in[6];
    const float* b2    = (const float*)d_in[7];
    float* out = (float*)d_out;

    int total_tokens = in_sizes[0] / HDIM;
    int M = total_tokens / 4;
    if (M > MAXM) M = MAXM;

    float *dX, *dH, *dW1, *dW2;
    cudaGetSymbolAddress((void**)&dX,  g_X);
    cudaGetSymbolAddress((void**)&dH,  g_H);
    cudaGetSymbolAddress((void**)&dW1, g_W1);
    cudaGetSymbolAddress((void**)&dW2, g_W2);

    cudaFuncSetAttribute(gemm_kernel, cudaFuncAttributeMaxDynamicSharedMemorySize, DSMEMB);

    meta_kernel<<<1, 32>>>(ss);
    gather_ln_kernel<<<M, 256>>>(vf, gamma, beta);

    wround_kernel<<<(IC * PH + 1023) / 1024, 256>>>(w1, dW1, IC * PH);
    wround_kernel<<<(PH * TH + 1023) / 1024, 256>>>(w2, dW2, PH * TH);

    dim3 g1(PH / 128, M / 128);
    gemm_kernel<<<g1, 256, DSMEMB>>>(dX, dW1, b1, dH, M, IC, PH, 1);

    dim3 g2(TH / 128, M / 128);
    gemm_kernel<<<g2, 256, DSMEMB>>>(dH, dW2, b2, out, M, PH, TH, 0);
}